// round 3
// baseline (speedup 1.0000x reference)
#include <cuda_runtime.h>
#include <cstdint>

#define COLS      16384
#define KSEL      64
#define NTHREADS  512
#define GPT       (COLS / (NTHREADS * 4))   // 8 float4-groups per thread
#define CAP       2048

// Monotonic uint key for float ordering (no NaNs expected in data).
__device__ __forceinline__ unsigned fkey(float f) {
    unsigned u = __float_as_uint(f);
    return u ^ ((unsigned)((int)u >> 31) | 0x80000000u);
}

// Inverse of fkey for the pivot; map NaN-encoding keys to +/-inf so that
// float comparisons remain consistent with key-space counting.
__device__ __forceinline__ float key_to_pivot(unsigned k) {
    unsigned bits = (k & 0x80000000u) ? (k & 0x7FFFFFFFu) : ~k;
    float f = __uint_as_float(bits);
    if (f != f) {
        f = (k & 0x80000000u) ? __uint_as_float(0x7F800000u)   // +inf
                              : __uint_as_float(0xFF800000u);  // -inf
    }
    return f;
}

__global__ void __launch_bounds__(NTHREADS, 2)
sparsify_topk_kernel(const float* __restrict__ x, float* __restrict__ out)
{
    __shared__ unsigned s_key[CAP];
    __shared__ int      s_idx[CAP];
    __shared__ int      s_cnt;
    __shared__ unsigned s_pk, s_lo, s_hi, s_tkey;
    __shared__ int      s_status;   // 0 retry, 2 final-pass(T==new pivot), 3 done

    const int    tid = threadIdx.x;
    const size_t row = blockIdx.x;
    const float4* __restrict__ vin  = (const float4*)(x   + row * (size_t)COLS);
    float4*       __restrict__ vout = (float4*)      (out + row * (size_t)COLS);

    if (tid == 0) {
        s_pk = fkey(2.4f);      // initial pivot: E[candidates] ~ 135 for N(0,1)
        s_lo = 0u;              // invariant: count(key >= s_lo) >= KSEL
        s_hi = 0xFFFFFFFFu;
        s_status = 0;
    }
    __syncthreads();

    bool finalPass = false;

    for (;;) {
        float pivotf = key_to_pivot(s_pk);
        if (tid == 0) s_cnt = 0;
        __syncthreads();

        // ---- front-batched loads: 8 LDG.128 in flight per warp ----
        float4 v[GPT];
        #pragma unroll
        for (int it = 0; it < GPT; ++it)
            v[it] = __ldcs(&vin[tid + it * NTHREADS]);

        #pragma unroll
        for (int it = 0; it < GPT; ++it) {
            int g = tid + it * NTHREADS;
            float m = fmaxf(fmaxf(v[it].x, v[it].y), fmaxf(v[it].z, v[it].w));
            if (m >= pivotf) {
                // rare path: ~135 groups out of 4096 per row
                float4 o;
                o.x = (v[it].x >= pivotf) ? v[it].x : 0.0f;
                o.y = (v[it].y >= pivotf) ? v[it].y : 0.0f;
                o.z = (v[it].z >= pivotf) ? v[it].z : 0.0f;
                o.w = (v[it].w >= pivotf) ? v[it].w : 0.0f;
                __stcs(&vout[g], o);
                int base = g * 4;
                if (v[it].x >= pivotf) { int p = atomicAdd(&s_cnt, 1); if (p < CAP) { s_key[p] = fkey(v[it].x); s_idx[p] = base + 0; } }
                if (v[it].y >= pivotf) { int p = atomicAdd(&s_cnt, 1); if (p < CAP) { s_key[p] = fkey(v[it].y); s_idx[p] = base + 1; } }
                if (v[it].z >= pivotf) { int p = atomicAdd(&s_cnt, 1); if (p < CAP) { s_key[p] = fkey(v[it].z); s_idx[p] = base + 2; } }
                if (v[it].w >= pivotf) { int p = atomicAdd(&s_cnt, 1); if (p < CAP) { s_key[p] = fkey(v[it].w); s_idx[p] = base + 3; } }
            } else {
                __stcs(&vout[g], make_float4(0.f, 0.f, 0.f, 0.f));
            }
        }
        __syncthreads();

        if (finalPass) return;       // out already exact (T == pivot), no fixup

        int cc = s_cnt;              // uniform: read after barrier
        if (cc >= KSEL && cc <= CAP) break;   // go select exact threshold

        // Bisection retry in key space (essentially never taken on this input)
        if (tid == 0) {
            if (cc < KSEL) {
                s_hi = s_pk;
                unsigned step = (s_pk - s_lo) >> 1;
                if (step == 0) { s_pk = s_lo; s_status = 2; }  // T == s_lo exactly
                else           { s_pk -= step; s_status = 0; }
            } else { // cc > CAP
                s_lo = s_pk;
                unsigned step = (s_hi - s_pk) >> 1;
                if (step == 0) { s_status = 3; }  // T == s_pk; out already correct
                else           { s_pk += step; s_status = 0; }
            }
        }
        __syncthreads();
        int st = s_status;           // uniform
        if (st == 3) return;
        if (st == 2) finalPass = true;
    }

    // --- exact selection: 64th largest key among c candidates (warp 0) ---
    int c = s_cnt;   // 64 <= c <= CAP
    if (tid < 32) {
        if (c <= 8 * 32) {
            // common case (c ~ 135): keys in registers, ballot+popc counting
            unsigned k[8];
            #pragma unroll
            for (int j = 0; j < 8; ++j) {
                int i = tid + j * 32;
                k[j] = (i < c) ? s_key[i] : 0u;
            }
            unsigned cur = 0;
            for (int b = 31; b >= 0; --b) {
                unsigned t = cur | (1u << b);
                int cnt = 0;
                #pragma unroll
                for (int j = 0; j < 8; ++j)
                    cnt += __popc(__ballot_sync(0xFFFFFFFFu, k[j] >= t));
                if (cnt >= KSEL) cur = t;
            }
            if (tid == 0) s_tkey = cur;
        } else {
            unsigned cur = 0;
            for (int b = 31; b >= 0; --b) {
                unsigned t = cur | (1u << b);
                int cnt = 0;
                for (int i = tid; i < c; i += 32)
                    cnt += (s_key[i] >= t) ? 1 : 0;
                cnt = __reduce_add_sync(0xFFFFFFFFu, cnt);
                if (cnt >= KSEL) cur = t;
            }
            if (tid == 0) s_tkey = cur;
        }
    }
    __syncthreads();

    // --- fixup: zero candidates strictly below the exact threshold ---
    unsigned T = s_tkey;
    float* orow = out + row * (size_t)COLS;
    for (int i = tid; i < c; i += NTHREADS) {
        if (s_key[i] < T) orow[s_idx[i]] = 0.0f;
    }
}

extern "C" void kernel_launch(void* const* d_in, const int* in_sizes, int n_in,
                              void* d_out, int out_size) {
    const float* x = (const float*)d_in[0];
    float* out = (float*)d_out;
    int rows = in_sizes[0] / COLS;
    sparsify_topk_kernel<<<rows, NTHREADS>>>(x, out);
}

// round 4
// speedup vs baseline: 1.2163x; 1.2163x over previous
#include <cuda_runtime.h>
#include <cstdint>

#define COLS      16384
#define KSEL      64
#define NTHREADS  512
#define GPT       (COLS / (NTHREADS * 4))   // 8 float4-groups per thread
#define CAP       2048

// Monotonic uint key for float ordering (no NaNs expected in data).
__device__ __forceinline__ unsigned fkey(float f) {
    unsigned u = __float_as_uint(f);
    return u ^ ((unsigned)((int)u >> 31) | 0x80000000u);
}

__device__ __forceinline__ float key_to_float(unsigned k) {
    unsigned bits = (k & 0x80000000u) ? (k ^ 0x80000000u) : ~k;
    return __uint_as_float(bits);
}

// Pivot for comparisons; map NaN-encoding keys to +/-inf so float compares
// stay consistent with key-space counting during bisection.
__device__ __forceinline__ float key_to_pivot(unsigned k) {
    float f = key_to_float(k);
    if (f != f) {
        f = (k & 0x80000000u) ? __uint_as_float(0x7F800000u)   // +inf
                              : __uint_as_float(0xFF800000u);  // -inf
    }
    return f;
}

__global__ void __launch_bounds__(NTHREADS, 2)
sparsify_topk_kernel(const float* __restrict__ x, float* __restrict__ out)
{
    __shared__ unsigned s_key[CAP];
    __shared__ int      s_idx[CAP];
    __shared__ int      s_cnt;
    __shared__ unsigned s_pk, s_lo, s_hi, s_tkey;
    __shared__ int      s_status;   // 0 retry, 1 select, 2 full-write fallback

    const int    tid = threadIdx.x;
    const size_t row = blockIdx.x;
    const float4* __restrict__ vin = (const float4*)(x + row * (size_t)COLS);
    float* __restrict__ orow = out + row * (size_t)COLS;

    if (tid == 0) {
        s_pk = fkey(2.4f);      // initial pivot: E[candidates] ~ 135 for N(0,1)
        s_lo = 0u;              // invariant: count(key >= s_lo) >= KSEL
        s_hi = 0xFFFFFFFFu;
    }
    __syncthreads();

    // ---- pivot loop: READ-ONLY candidate collection ----
    for (;;) {
        float pivotf = key_to_pivot(s_pk);
        if (tid == 0) s_cnt = 0;
        __syncthreads();

        // front-batched loads: 8 LDG.128 in flight per warp, no stores at all
        float4 v[GPT];
        #pragma unroll
        for (int it = 0; it < GPT; ++it)
            v[it] = __ldcs(&vin[tid + it * NTHREADS]);

        #pragma unroll
        for (int it = 0; it < GPT; ++it) {
            float m = fmaxf(fmaxf(v[it].x, v[it].y), fmaxf(v[it].z, v[it].w));
            if (m >= pivotf) {
                int base = (tid + it * NTHREADS) * 4;
                if (v[it].x >= pivotf) { int p = atomicAdd(&s_cnt, 1); if (p < CAP) { s_key[p] = fkey(v[it].x); s_idx[p] = base + 0; } }
                if (v[it].y >= pivotf) { int p = atomicAdd(&s_cnt, 1); if (p < CAP) { s_key[p] = fkey(v[it].y); s_idx[p] = base + 1; } }
                if (v[it].z >= pivotf) { int p = atomicAdd(&s_cnt, 1); if (p < CAP) { s_key[p] = fkey(v[it].z); s_idx[p] = base + 2; } }
                if (v[it].w >= pivotf) { int p = atomicAdd(&s_cnt, 1); if (p < CAP) { s_key[p] = fkey(v[it].w); s_idx[p] = base + 3; } }
            }
        }
        __syncthreads();

        int cc = s_cnt;              // uniform: read after barrier
        if (cc >= KSEL && cc <= CAP) {
            if (tid == 0) s_status = 1;
            __syncthreads();
            break;
        }

        // Bisection retry in key space (essentially never taken on this input)
        if (tid == 0) {
            s_status = 0;
            if (cc < KSEL) {
                s_hi = s_pk;
                unsigned step = (s_pk - s_lo) >> 1;
                if (step == 0) { s_pk = s_lo; s_status = 2; }  // T == s_lo exactly
                else           { s_pk -= step; }
            } else { // cc > CAP
                s_lo = s_pk;
                unsigned step = (s_hi - s_pk) >> 1;
                if (step == 0) { s_tkey = s_pk; s_status = 2; } // T == s_pk
                else           { s_pk += step; }
            }
        }
        __syncthreads();
        if (s_status == 2) {
            // pathological fallback: full masked write pass with exact T
            float Tf = key_to_pivot(s_pk);
            float4 v[GPT];
            #pragma unroll
            for (int it = 0; it < GPT; ++it)
                v[it] = __ldcs(&vin[tid + it * NTHREADS]);
            float4* vout = (float4*)orow;
            #pragma unroll
            for (int it = 0; it < GPT; ++it) {
                float4 o;
                o.x = (v[it].x >= Tf) ? v[it].x : 0.0f;
                o.y = (v[it].y >= Tf) ? v[it].y : 0.0f;
                o.z = (v[it].z >= Tf) ? v[it].z : 0.0f;
                o.w = (v[it].w >= Tf) ? v[it].w : 0.0f;
                vout[tid + it * NTHREADS] = o;
            }
            return;
        }
    }

    // --- exact selection: 64th largest key among c candidates (warp 0) ---
    int c = s_cnt;   // KSEL <= c <= CAP
    if (tid < 32) {
        if (c <= 8 * 32) {
            // common case (c ~ 135): keys in registers, ballot+popc counting
            unsigned k[8];
            #pragma unroll
            for (int j = 0; j < 8; ++j) {
                int i = tid + j * 32;
                k[j] = (i < c) ? s_key[i] : 0u;
            }
            unsigned cur = 0;
            for (int b = 31; b >= 0; --b) {
                unsigned t = cur | (1u << b);
                int cnt = 0;
                #pragma unroll
                for (int j = 0; j < 8; ++j)
                    cnt += __popc(__ballot_sync(0xFFFFFFFFu, k[j] >= t));
                if (cnt >= KSEL) cur = t;
            }
            if (tid == 0) s_tkey = cur;
        } else {
            unsigned cur = 0;
            for (int b = 31; b >= 0; --b) {
                unsigned t = cur | (1u << b);
                int cnt = 0;
                for (int i = tid; i < c; i += 32)
                    cnt += (s_key[i] >= t) ? 1 : 0;
                cnt = __reduce_add_sync(0xFFFFFFFFu, cnt);
                if (cnt >= KSEL) cur = t;
            }
            if (tid == 0) s_tkey = cur;
        }
    }
    __syncthreads();

    // --- scatter: write only the kept values (>= T, including ties) ---
    unsigned T = s_tkey;
    for (int i = tid; i < c; i += NTHREADS) {
        unsigned k = s_key[i];
        if (k >= T) orow[s_idx[i]] = key_to_float(k);
    }
}

extern "C" void kernel_launch(void* const* d_in, const int* in_sizes, int n_in,
                              void* d_out, int out_size) {
    const float* x = (const float*)d_in[0];
    float* out = (float*)d_out;
    int rows = in_sizes[0] / COLS;
    cudaMemsetAsync(d_out, 0, (size_t)out_size * sizeof(float), 0);
    sparsify_topk_kernel<<<rows, NTHREADS>>>(x, out);
}